// round 9
// baseline (speedup 1.0000x reference)
#include <cuda_runtime.h>
#include <cstdint>

// Problem constants
#define NN 40000
#define EE 640000
#define DD 128
#define EDD 16
#define LL 3
#define BN_INV 0.99999500003749978f  // 1/sqrt(1+1e-5)

// Scratch (no cudaMalloc allowed)
__device__ float  g_h[(size_t)NN * DD];
__device__ float  g_h2[(size_t)NN * DD];
__device__ float  g_agg[(size_t)NN * DD];
__device__ float  g_t[(size_t)NN * 2 * DD];
__device__ float2 g_pre[NN];
__device__ int    g_deg[NN];
__device__ int    g_off[NN + 1];
__device__ int    g_cur[NN];
__device__ int2   g_ecsr[EE];   // (src node, original edge id) per CSR slot

// ---- f32x2 helpers --------------------------------------------------------
__device__ __forceinline__ unsigned long long pack2(float lo, float hi) {
    unsigned long long r;
    asm("mov.b64 %0, {%1, %2};" : "=l"(r) : "f"(lo), "f"(hi));
    return r;
}
__device__ __forceinline__ void ffma2(unsigned long long& d,
                                      unsigned long long a,
                                      unsigned long long b) {
    asm("fma.rn.f32x2 %0, %1, %2, %0;" : "+l"(d) : "l"(a), "l"(b));
}
__device__ __forceinline__ void unpack2(unsigned long long v, float& lo, float& hi) {
    asm("mov.b64 {%0, %1}, %2;" : "=f"(lo), "=f"(hi) : "l"(v));
}
__device__ __forceinline__ float fold2(unsigned long long v) {
    float lo, hi; unpack2(v, lo, hi); return lo + hi;
}

// ---------------------------------------------------------------------------
// CSR build (once per call): zero -> count -> scan -> fill
// ---------------------------------------------------------------------------
__global__ void zero_deg_kernel(int* __restrict__ deg) {
    int i = blockIdx.x * blockDim.x + threadIdx.x;
    if (i < NN) deg[i] = 0;
}

__global__ void count_kernel(const int* __restrict__ dst, int* __restrict__ deg) {
    int e = blockIdx.x * blockDim.x + threadIdx.x;
    if (e < EE) atomicAdd(&deg[dst[e]], 1);
}

__global__ __launch_bounds__(1024)
void scan_kernel(const int* __restrict__ deg, int* __restrict__ off,
                 int* __restrict__ cur) {
    __shared__ int part[1024];
    const int tid = threadIdx.x;
    const int per = (NN + 1023) / 1024;   // 40
    const int base = tid * per;
    int s = 0;
#pragma unroll 4
    for (int i = 0; i < per; i++) {
        const int n = base + i;
        if (n < NN) s += deg[n];
    }
    part[tid] = s;
    __syncthreads();
    for (int ofs = 1; ofs < 1024; ofs <<= 1) {
        int v = (tid >= ofs) ? part[tid - ofs] : 0;
        __syncthreads();
        part[tid] += v;
        __syncthreads();
    }
    int run = (tid > 0) ? part[tid - 1] : 0;   // exclusive prefix
    for (int i = 0; i < per; i++) {
        const int n = base + i;
        if (n < NN) {
            off[n] = run;
            cur[n] = run;
            run += deg[n];
        }
    }
    if (tid == 1023) off[NN] = EE;
}

__global__ void fill_kernel(const int* __restrict__ src,
                            const int* __restrict__ dst,
                            int* __restrict__ cur,
                            int2* __restrict__ ecsr) {
    int e = blockIdx.x * blockDim.x + threadIdx.x;
    if (e >= EE) return;
    const int d = dst[e];
    const int p = atomicAdd(&cur[d], 1);
    ecsr[p] = make_int2(src[e], e);
}

// ---------------------------------------------------------------------------
// prep: pre[n] = (h[n]·attn_W[0:128], h[n]·attn_W[128:256]). Warp per node.
// ---------------------------------------------------------------------------
__global__ __launch_bounds__(128)
void prep_kernel(const float* __restrict__ h,
                 const float* __restrict__ attn_W,   // [256]
                 float2* __restrict__ pre) {
    const int warp = (blockIdx.x * blockDim.x + threadIdx.x) >> 5;
    const int lane = threadIdx.x & 31;
    if (warp >= NN) return;
    const int d0 = lane * 4;
    const float4 hv = *(const float4*)(h + (size_t)warp * DD + d0);
    const float4 wi = *(const float4*)(attn_W + d0);
    const float4 wj = *(const float4*)(attn_W + DD + d0);
    float pi = hv.x * wi.x + hv.y * wi.y + hv.z * wi.z + hv.w * wi.w;
    float pj = hv.x * wj.x + hv.y * wj.y + hv.z * wj.z + hv.w * wj.w;
#pragma unroll
    for (int off = 16; off > 0; off >>= 1) {
        pi += __shfl_xor_sync(0xffffffffu, pi, off);
        pj += __shfl_xor_sync(0xffffffffu, pj, off);
    }
    if (lane == 0) pre[warp] = make_float2(pi, pj);
}

// ---------------------------------------------------------------------------
// per-edge accumulate helper
// ---------------------------------------------------------------------------
__device__ __forceinline__ void accum_edge(
    float4& acc, float a, float vmask, const float4 xj,
    const ulonglong2 qa, const ulonglong2 qb,
    const ulonglong2 qc, const ulonglong2 qd,
    const unsigned long long* __restrict__ wE2,
    const unsigned long long* __restrict__ ebp) {
    const unsigned long long ep[8] = {qa.x, qa.y, qb.x, qb.y,
                                      qc.x, qc.y, qd.x, qd.y};
    unsigned long long av0 = ebp[0], av1 = ebp[1], av2 = ebp[2], av3 = ebp[3];
#pragma unroll
    for (int k2 = 0; k2 < 8; k2++) {
        ffma2(av0, ep[k2], wE2[k2 * 4 + 0]);
        ffma2(av1, ep[k2], wE2[k2 * 4 + 1]);
        ffma2(av2, ep[k2], wE2[k2 * 4 + 2]);
        ffma2(av3, ep[k2], wE2[k2 * 4 + 3]);
    }
    acc.x = fmaf(fmaxf(fmaf(xj.x, a, fold2(av0)), 0.0f), vmask, acc.x);
    acc.y = fmaf(fmaxf(fmaf(xj.y, a, fold2(av1)), 0.0f), vmask, acc.y);
    acc.z = fmaf(fmaxf(fmaf(xj.z, a, fold2(av2)), 0.0f), vmask, acc.z);
    acc.w = fmaf(fmaxf(fmaf(xj.w, a, fold2(av3)), 0.0f), vmask, acc.w);
}

// ---------------------------------------------------------------------------
// CSR edge kernel v2: warp per destination node, lane-vector index fetch
// (one LDG per <=32 edges, indices broadcast via shfl), 4-edge load batches.
// ---------------------------------------------------------------------------
__global__ __launch_bounds__(128, 3)
void edge_csr_kernel(const float* __restrict__ h,
                     const float* __restrict__ edge_attr,
                     const int* __restrict__ off,
                     const int2* __restrict__ ecsr,
                     const float* __restrict__ edge_W,   // [16,128]
                     const float* __restrict__ edge_b,   // [128]
                     const float2* __restrict__ pre,     // [N]
                     const float* __restrict__ attn_b,   // [1]
                     const float* __restrict__ eps_l,
                     float* __restrict__ agg) {
    const int lane = threadIdx.x & 31;
    const int node = (blockIdx.x * blockDim.x + threadIdx.x) >> 5;
    if (node >= NN) return;
    const int d0 = lane * 4;

    // edge weights packed (k even, k odd) per output dim
    unsigned long long wE2[32];
#pragma unroll
    for (int k2 = 0; k2 < 8; k2++) {
        const float4 wa = *(const float4*)(edge_W + (2 * k2) * DD + d0);
        const float4 wb = *(const float4*)(edge_W + (2 * k2 + 1) * DD + d0);
        wE2[k2 * 4 + 0] = pack2(wa.x, wb.x);
        wE2[k2 * 4 + 1] = pack2(wa.y, wb.y);
        wE2[k2 * 4 + 2] = pack2(wa.z, wb.z);
        wE2[k2 * 4 + 3] = pack2(wa.w, wb.w);
    }
    unsigned long long ebp[4];
    {
        const float4 eb = *(const float4*)(edge_b + d0);
        ebp[0] = pack2(eb.x, 0.0f); ebp[1] = pack2(eb.y, 0.0f);
        ebp[2] = pack2(eb.z, 0.0f); ebp[3] = pack2(eb.w, 0.0f);
    }
    const int beg = off[node], end = off[node + 1];
    const int deg = end - beg;
    const int m = (deg < 32) ? deg : 32;
    const float pd = __ldg(&pre[node].x) + attn_b[0];

    float4 acc;
    {
        const float s = 1.0f + eps_l[0];
        const float4 hv = *(const float4*)(h + (size_t)node * DD + d0);
        acc.x = hv.x * s; acc.y = hv.y * s; acc.z = hv.z * s; acc.w = hv.w * s;
    }

    // One lane-vector load covers up to 32 edges of this node.
    int2 se = make_int2(0, 0);
    if (lane < m) se = __ldg(&ecsr[beg + lane]);

    const int ngrp = (m + 3) >> 2;
#pragma unroll 1
    for (int g = 0; g < ngrp; g++) {
        const int base = g * 4;
        int  sI[4], iI[4];
        float vm[4];
#pragma unroll
        for (int u = 0; u < 4; u++) {
            const int e = base + u;
            sI[u] = __shfl_sync(0xffffffffu, se.x, e & 31);
            iI[u] = __shfl_sync(0xffffffffu, se.y, e & 31);
            vm[u] = (e < m) ? 1.0f : 0.0f;
        }
        // Batched loads: 4 gathers + 4 attr rows + 4 pre scalars
        float4 xj[4]; float pj[4];
        ulonglong2 q[4][4];
#pragma unroll
        for (int u = 0; u < 4; u++) {
            xj[u] = *(const float4*)(h + (size_t)sI[u] * DD + d0);
            pj[u] = __ldg(&pre[sI[u]].y);
            const ulonglong2* ea = (const ulonglong2*)(edge_attr + (size_t)iI[u] * EDD);
            q[u][0] = __ldg(ea + 0); q[u][1] = __ldg(ea + 1);
            q[u][2] = __ldg(ea + 2); q[u][3] = __ldg(ea + 3);
        }
#pragma unroll
        for (int u = 0; u < 4; u++) {
            const float a = 1.0f / (1.0f + __expf(-(pd + pj[u])));
            accum_edge(acc, a, vm[u], xj[u],
                       q[u][0], q[u][1], q[u][2], q[u][3], wE2, ebp);
        }
    }

    // Rare overflow: degree > 32
#pragma unroll 1
    for (int j = beg + 32; j < end; j++) {
        const int2 e2 = __ldg(&ecsr[j]);
        const float4 xj = *(const float4*)(h + (size_t)e2.x * DD + d0);
        const float pj = __ldg(&pre[e2.x].y);
        const ulonglong2* ea = (const ulonglong2*)(edge_attr + (size_t)e2.y * EDD);
        const float a = 1.0f / (1.0f + __expf(-(pd + pj)));
        accum_edge(acc, a, 1.0f, xj,
                   __ldg(ea + 0), __ldg(ea + 1), __ldg(ea + 2), __ldg(ea + 3),
                   wE2, ebp);
    }

    *(float4*)(agg + (size_t)node * DD + d0) = acc;
}

// ---------------------------------------------------------------------------
// SGEMM: 128 threads, 128x128 tile, 16x8 per-thread, scalar FFMA core,
// 4-stage cp.async(B) pipeline, ONE barrier per k-tile (race-free at S=4).
// ---------------------------------------------------------------------------
__global__ __launch_bounds__(128, 3)
void sgemm_kernel(const float* __restrict__ A, const float* __restrict__ B,
                  const float* __restrict__ bias,
                  const float* __restrict__ bn_g, const float* __restrict__ bn_b,
                  float* __restrict__ C,
                  int M, int K, int Nc, int do_relu, int do_bn) {
    __shared__ float As[4][8][128];   // [stage][k][row]
    __shared__ float Bs[4][8][128];   // [stage][k][col]

    const int tid = threadIdx.x;
    const int tx = tid & 15;
    const int ty = tid >> 4;
    const int row0 = blockIdx.y * 128;
    const int col0 = blockIdx.x * 128;

    const int a_row = tid >> 1;
    const int a_col = (tid & 1) * 4;
    const int b_row = tid >> 4;
    const int b_col = (tid & 15) * 8;

    const int gr1 = row0 + a_row, gr2 = gr1 + 64;
    const bool v1 = gr1 < M, v2 = gr2 < M;
    const float* aptr1 = A + (size_t)gr1 * K + a_col;
    const float* aptr2 = A + (size_t)gr2 * K + a_col;
    const float* bptr  = B + (size_t)b_row * Nc + col0 + b_col;

    const int nt = K >> 3;
    const float4 f40 = make_float4(0.f, 0.f, 0.f, 0.f);
    float4 ar0, ar1;

#define LDG_A(k0) { ar0 = v1 ? *(const float4*)(aptr1 + (k0)) : f40; \
                    ar1 = v2 ? *(const float4*)(aptr2 + (k0)) : f40; }
#define STS_A(stg) { As[stg][a_col+0][a_row] = ar0.x; As[stg][a_col+1][a_row] = ar0.y; \
                     As[stg][a_col+2][a_row] = ar0.z; As[stg][a_col+3][a_row] = ar0.w; \
                     As[stg][a_col+0][a_row+64] = ar1.x; As[stg][a_col+1][a_row+64] = ar1.y; \
                     As[stg][a_col+2][a_row+64] = ar1.z; As[stg][a_col+3][a_row+64] = ar1.w; }
#define CP_B(stg, k0) { \
    uint32_t _d = (uint32_t)__cvta_generic_to_shared(&Bs[stg][b_row][b_col]); \
    const float* _s = bptr + (size_t)(k0) * Nc; \
    asm volatile("cp.async.cg.shared.global [%0], [%1], 16;\n\t" \
                 "cp.async.cg.shared.global [%2], [%3], 16;\n\t" \
                 "cp.async.commit_group;\n" \
                 :: "r"(_d), "l"(_s), "r"(_d + 16), "l"(_s + 4) : "memory"); }

    float acc[16][8];
#pragma unroll
    for (int i = 0; i < 16; i++)
#pragma unroll
        for (int j = 0; j < 8; j++) acc[i][j] = 0.0f;

    // Prologue: tiles 0 and 1
    LDG_A(0); CP_B(0, 0); STS_A(0);
    LDG_A(8); CP_B(1, 8);

#pragma unroll 1
    for (int t = 0; t < nt; t++) {
        const int st = t & 3;
        if (t + 1 < nt) STS_A((t + 1) & 3);
        if (t + 2 < nt) { const int k0 = (t + 2) * 8; LDG_A(k0); CP_B((t + 2) & 3, k0); }
        const int rem = nt - 1 - t;
        if (rem >= 2)      asm volatile("cp.async.wait_group 2;" ::: "memory");
        else if (rem == 1) asm volatile("cp.async.wait_group 1;" ::: "memory");
        else               asm volatile("cp.async.wait_group 0;" ::: "memory");
        __syncthreads();

#pragma unroll
        for (int k = 0; k < 8; k++) {
            float af[16], bf[8];
            *(float4*)&af[0]  = *(const float4*)&As[st][k][ty * 16];
            *(float4*)&af[4]  = *(const float4*)&As[st][k][ty * 16 + 4];
            *(float4*)&af[8]  = *(const float4*)&As[st][k][ty * 16 + 8];
            *(float4*)&af[12] = *(const float4*)&As[st][k][ty * 16 + 12];
            *(float4*)&bf[0]  = *(const float4*)&Bs[st][k][tx * 8];
            *(float4*)&bf[4]  = *(const float4*)&Bs[st][k][tx * 8 + 4];
#pragma unroll
            for (int i = 0; i < 16; i++)
#pragma unroll
                for (int j = 0; j < 8; j++)
                    acc[i][j] = fmaf(af[i], bf[j], acc[i][j]);
        }
    }

    // Epilogue
    float bi[8], g[8], bb[8];
#pragma unroll
    for (int j = 0; j < 8; j++) {
        const int c = col0 + tx * 8 + j;
        bi[j] = bias[c];
        if (do_bn) { g[j] = bn_g[c]; bb[j] = bn_b[c]; }
    }
#pragma unroll
    for (int i = 0; i < 16; i++) {
        const int r = row0 + ty * 16 + i;
        if (r >= M) continue;
        float v[8];
#pragma unroll
        for (int j = 0; j < 8; j++) {
            float t = acc[i][j] + bi[j];
            if (do_bn) t = fmaf(g[j] * BN_INV, t, bb[j]);
            if (do_relu) t = fmaxf(t, 0.0f);
            v[j] = t;
        }
        float* cp = C + (size_t)r * Nc + col0 + tx * 8;
        *(float4*)cp       = make_float4(v[0], v[1], v[2], v[3]);
        *(float4*)(cp + 4) = make_float4(v[4], v[5], v[6], v[7]);
    }
#undef LDG_A
#undef STS_A
#undef CP_B
}

// ---------------------------------------------------------------------------
extern "C" void kernel_launch(void* const* d_in, const int* in_sizes, int n_in,
                              void* d_out, int out_size) {
    const float* x         = (const float*)d_in[0];
    const float* edge_attr = (const float*)d_in[1];
    const float* node_W    = (const float*)d_in[2];
    const float* node_b    = (const float*)d_in[3];
    const float* edge_W    = (const float*)d_in[4];
    const float* edge_b    = (const float*)d_in[5];
    const float* attn_W    = (const float*)d_in[6];
    const float* attn_b    = (const float*)d_in[7];
    const float* eps       = (const float*)d_in[8];
    const float* W1        = (const float*)d_in[9];
    const float* b1        = (const float*)d_in[10];
    const float* bn1_g     = (const float*)d_in[11];
    const float* bn1_b     = (const float*)d_in[12];
    const float* W2        = (const float*)d_in[13];
    const float* b2        = (const float*)d_in[14];
    const float* bn_g      = (const float*)d_in[15];
    const float* bn_b      = (const float*)d_in[16];
    const int*   edge_index= (const int*)d_in[17];

    float *hA, *hB, *agg, *tbuf; float2* pre;
    int *deg, *off, *cur; int2* ecsr;
    cudaGetSymbolAddress((void**)&hA,   g_h);
    cudaGetSymbolAddress((void**)&hB,   g_h2);
    cudaGetSymbolAddress((void**)&agg,  g_agg);
    cudaGetSymbolAddress((void**)&tbuf, g_t);
    cudaGetSymbolAddress((void**)&pre,  g_pre);
    cudaGetSymbolAddress((void**)&deg,  g_deg);
    cudaGetSymbolAddress((void**)&off,  g_off);
    cudaGetSymbolAddress((void**)&cur,  g_cur);
    cudaGetSymbolAddress((void**)&ecsr, g_ecsr);

    const int* src_arr = edge_index;
    const int* dst_arr = edge_index + EE;
    const int mblk = (NN + 127) / 128;     // 313

    // CSR build
    zero_deg_kernel<<<(NN + 255) / 256, 256>>>(deg);
    count_kernel<<<(EE + 255) / 256, 256>>>(dst_arr, deg);
    scan_kernel<<<1, 1024>>>(deg, off, cur);
    fill_kernel<<<(EE + 255) / 256, 256>>>(src_arr, dst_arr, cur, ecsr);

    // node encoder: h = x @ node_W + node_b
    sgemm_kernel<<<dim3(1, mblk), 128>>>(x, node_W, node_b, nullptr, nullptr,
                                         hA, NN, DD, DD, 0, 0);

    const float* hcur = hA;
    float* hnext = hB;
    for (int l = 0; l < LL; l++) {
        prep_kernel<<<10000, 128>>>(hcur, attn_W + (size_t)l * 2 * DD, pre);
        edge_csr_kernel<<<10000, 128>>>(hcur, edge_attr, off, ecsr,
                                        edge_W + (size_t)l * EDD * DD,
                                        edge_b + (size_t)l * DD,
                                        pre, attn_b + l, eps + l, agg);
        // t = relu(bn1(agg @ W1 + b1))   [N,128]@[128,256]
        sgemm_kernel<<<dim3(2, mblk), 128>>>(agg, W1 + (size_t)l * DD * 2 * DD,
                                             b1 + (size_t)l * 2 * DD,
                                             bn1_g + (size_t)l * 2 * DD,
                                             bn1_b + (size_t)l * 2 * DD,
                                             tbuf, NN, DD, 2 * DD, 1, 1);
        // h' = [relu] bn(t @ W2 + b2)    [N,256]@[256,128]
        float* outp = (l == LL - 1) ? (float*)d_out : hnext;
        sgemm_kernel<<<dim3(1, mblk), 128>>>(tbuf, W2 + (size_t)l * 2 * DD * DD,
                                             b2 + (size_t)l * DD,
                                             bn_g + (size_t)l * DD,
                                             bn_b + (size_t)l * DD,
                                             outp, NN, 2 * DD, DD, (l < LL - 1) ? 1 : 0, 1);
        if (l < LL - 1) {
            hcur = outp;
            hnext = (outp == hA) ? hB : hA;
        }
    }
}